// round 9
// baseline (speedup 1.0000x reference)
#include <cuda_runtime.h>
#include <cuda_fp16.h>

// Problem constants (fixed by the dataset)
#define T_STEPS 8
#define NN      100000
#define EE      1600000
#define FLAT    4096    // 64*64
#define BN      1024    // bottleneck
#define NB_ODE  128     // persistent ODE grid (1 block/SM, co-resident)
#define NB_SCAN 98      // ceil(NN/1024)
#define EPB     64      // edges per block in edge_kernel

typedef unsigned long long u64;

// ---------------- packed fp32x2 helpers (sm_103a FFMA2) ----------------
#define FMA2(acc, a, b) \
    asm("fma.rn.f32x2 %0, %1, %2, %0;" : "+l"(acc) : "l"(a), "l"(b))

__device__ __forceinline__ u64 dup2(float x) {
    u64 r; asm("mov.b64 %0, {%1, %1};" : "=l"(r) : "f"(x)); return r;
}
__device__ __forceinline__ u64 pack2(float x, float y) {
    u64 r; asm("mov.b64 %0, {%1, %2};" : "=l"(r) : "f"(x), "f"(y)); return r;
}
__device__ __forceinline__ float2 unpack2(u64 v) {
    float2 r; asm("mov.b64 {%0, %1}, %2;" : "=f"(r.x), "=f"(r.y) : "l"(v)); return r;
}

// ---------------- device scratch (no allocs allowed) ----------------
__device__ float  g_w[FLAT];
__device__ float  g_ws[FLAT];
__device__ float  g_t[BN];
__device__ float  g_W1t[BN * FLAT];   // transposed: row j (1024 rows) x k (4096)
__device__ float  g_W2t[FLAT * BN];   // transposed: row j (4096 rows) x k (1024)
__device__ unsigned g_barcnt;
__device__ float  g_dis[NN];
__device__ int    g_cnt[NN];        // in-degree (no self)
__device__ int    g_base[NN + 1];   // CSR row offsets (by destination)
__device__ int    g_cur[NN];        // placement cursors
__device__ int    g_src[EE];        // CSR: source node per in-edge
__device__ int    g_bsum[NB_SCAN];
__device__ int    g_boff[NB_SCAN];
__device__ __align__(16) __half2 g_zh[NN * 32];   // dis[n]*(x W_T)  fp16 [N,64]
__device__ __align__(16) __half2 g_hAh[NN * 32];  // h@A+b1 fp16      [N,64]
__device__ __align__(16) __half2 g_hBh[NN * 32];  // h@B    fp16      [N,64]

// ---------------- init: copy w0, zero counters, reset barrier ----------------
__global__ void init_kernel(const float* __restrict__ iw, int n) {
    int i = blockIdx.x * 256 + threadIdx.x;
    if (i == 0) g_barcnt = 0u;
    if (i < FLAT) g_w[i] = iw[i];
    if (i < n)    g_cnt[i] = 0;
}

// ---------------- in-degree count ----------------
__global__ void count_kernel(const int* __restrict__ ei, int e) {
    int i = blockIdx.x * 256 + threadIdx.x;
    if (i < e) atomicAdd(&g_cnt[ei[e + i]], 1);
}

// ---------------- dis = rsqrt(deg), deg = cnt + 1 (self loop) ----------------
__global__ void dis_kernel(int n) {
    int i = blockIdx.x * 256 + threadIdx.x;
    if (i < n) g_dis[i] = rsqrtf(1.0f + (float)g_cnt[i]);
}

// ---------------- CSR offset scan (3 small kernels) ----------------
__global__ void scan1_kernel(int n) {            // block sums
    __shared__ int sm_[1024];
    int i = blockIdx.x * 1024 + threadIdx.x;
    sm_[threadIdx.x] = (i < n) ? g_cnt[i] : 0;
    __syncthreads();
#pragma unroll
    for (int o = 512; o; o >>= 1) {
        if (threadIdx.x < o) sm_[threadIdx.x] += sm_[threadIdx.x + o];
        __syncthreads();
    }
    if (threadIdx.x == 0) g_bsum[blockIdx.x] = sm_[0];
}

__global__ void scan2_kernel(int nb) {           // serial scan of block sums
    __shared__ int sb[NB_SCAN];
    if (threadIdx.x < nb) sb[threadIdx.x] = g_bsum[threadIdx.x];
    __syncthreads();
    if (threadIdx.x == 0) {
        int run = 0;
        for (int b = 0; b < nb; ++b) { g_boff[b] = run; run += sb[b]; }
        g_base[NN] = run;            // == EE
    }
}

__global__ void scan3_kernel(int n) {            // in-block exclusive scan + offset
    __shared__ int sm_[1024];
    int i = blockIdx.x * 1024 + threadIdx.x;
    int v = (i < n) ? g_cnt[i] : 0;
    sm_[threadIdx.x] = v;
    __syncthreads();
#pragma unroll
    for (int o = 1; o < 1024; o <<= 1) {         // Hillis-Steele inclusive
        int t = (threadIdx.x >= o) ? sm_[threadIdx.x - o] : 0;
        __syncthreads();
        sm_[threadIdx.x] += t;
        __syncthreads();
    }
    if (i < n) {
        int excl = sm_[threadIdx.x] - v + g_boff[blockIdx.x];
        g_base[i] = excl;
        g_cur[i]  = excl;
    }
}

// ---------------- CSR placement ----------------
__global__ void place_kernel(const int* __restrict__ ei, int e) {
    int i = blockIdx.x * 256 + threadIdx.x;
    if (i < e) {
        int c = ei[e + i];
        int p = atomicAdd(&g_cur[c], 1);
        g_src[p] = ei[i];
    }
}

// ---------------- 32x32 tiled transpose: dst[C][R] = src[R][C]^T ----------------
__global__ void transpose_kernel(const float* __restrict__ src, float* __restrict__ dst,
                                 int R, int C) {
    __shared__ float tile[32][33];
    int bx = blockIdx.x * 32, by = blockIdx.y * 32;
    int x = bx + threadIdx.x;
#pragma unroll
    for (int i = 0; i < 32; i += 8) {
        int y = by + threadIdx.y + i;
        tile[threadIdx.y + i][threadIdx.x] = src[(size_t)y * C + x];
    }
    __syncthreads();
    int x2 = by + threadIdx.x;
#pragma unroll
    for (int i = 0; i < 32; i += 8) {
        int y2 = bx + threadIdx.y + i;
        dst[(size_t)y2 * R + x2] = tile[threadIdx.x][threadIdx.y + i];
    }
}

// ---------------- fast grid barrier: monotonic counter, acquire/release ----------------
__device__ __forceinline__ void gridsync(unsigned target) {
    __syncthreads();
    if (threadIdx.x == 0) {
        asm volatile("red.add.release.gpu.u32 [%0], %1;"
                     :: "l"(&g_barcnt), "r"(1u) : "memory");
        unsigned v;
        do {
            asm volatile("ld.acquire.gpu.u32 %0, [%1];"
                         : "=r"(v) : "l"(&g_barcnt) : "memory");
        } while (v < target);
    }
    __syncthreads();
}

// ---------------- persistent ODE (unchanged) ----------------
#define ODE_SMEM_FLOATS (32768 + 4096 + 1024 + 32)

__global__ __launch_bounds__(1024, 1)
void ode_persist(const float* __restrict__ b1, const float* __restrict__ b2, float h) {
    extern __shared__ float sm[];
    float* sW1 = sm;
    float* sw  = sm + 32768;
    float* st  = sm + 32768 + 4096;
    float* red = sm + 32768 + 4096 + 1024;   // [8 groups][4 warps]

    const int tid  = threadIdx.x;
    const int b    = blockIdx.x;
    const int lane = tid & 31;
    const int wid  = tid >> 5;
    const int grp  = tid >> 7;
    const int tin  = tid & 127;
    const int wgrp = tin >> 5;

    {
        const float4* src = (const float4*)(g_W1t + ((size_t)b * 8) * 4096);
        float4* dst = (float4*)sW1;
#pragma unroll
        for (int i = 0; i < 8; ++i) dst[tid + 1024 * i] = src[tid + 1024 * i];
    }
    float4 w2r[8];
    {
        const float4* src = (const float4*)(g_W2t + ((size_t)(b * 32 + wid)) * 1024);
#pragma unroll
        for (int i = 0; i < 8; ++i) w2r[i] = src[lane + 32 * i];
    }
    const int   j2  = b * 32 + wid;
    const float b2j = b2[j2];
    float wcur = g_w[j2];
    float k1 = 0.f, k2 = 0.f, k3 = 0.f;
    unsigned tgt = 0;
    __syncthreads();

    for (int stage = 0; stage < 4 * (T_STEPS - 1); ++stage) {
        const int st4 = stage & 3;
        {
            const float4* win = (const float4*)(st4 == 0 ? g_w : g_ws);
            ((float4*)sw)[tid] = __ldcg(win + tid);
        }
        __syncthreads();

        {
            const float4* wrow = (const float4*)(sW1 + (size_t)grp * 4096);
            const float4* sw4  = (const float4*)sw;
            float s = 0.f;
#pragma unroll
            for (int i = 0; i < 8; ++i) {
                float4 a = wrow[tin + 128 * i];
                float4 v = sw4[tin + 128 * i];
                s += a.x * v.x + a.y * v.y + a.z * v.z + a.w * v.w;
            }
#pragma unroll
            for (int o = 16; o; o >>= 1) s += __shfl_xor_sync(0xffffffffu, s, o);
            if (lane == 0) red[grp * 4 + wgrp] = s;
        }
        __syncthreads();
        if (tid < 8) {
            float tot = red[tid * 4] + red[tid * 4 + 1] + red[tid * 4 + 2] + red[tid * 4 + 3];
            g_t[b * 8 + tid] = tanhf(tot + b1[b * 8 + tid]);
        }
        tgt += NB_ODE;
        gridsync(tgt);

        if (tid < 256) ((float4*)st)[tid] = __ldcg(((const float4*)g_t) + tid);
        __syncthreads();
        {
            const float4* st4p = (const float4*)st;
            float s = 0.f;
#pragma unroll
            for (int i = 0; i < 8; ++i) {
                float4 a = w2r[i];
                float4 v = st4p[lane + 32 * i];
                s += a.x * v.x + a.y * v.y + a.z * v.z + a.w * v.w;
            }
#pragma unroll
            for (int o = 16; o; o >>= 1) s += __shfl_xor_sync(0xffffffffu, s, o);
            if (lane == 0) {
                float z = s + b2j;
                if (st4 == 0) {
                    k1 = z;
                    g_ws[j2] = wcur + (h * (1.f / 3.f)) * z;
                } else if (st4 == 1) {
                    k2 = z;
                    g_ws[j2] = wcur + h * (z - k1 * (1.f / 3.f));
                } else if (st4 == 2) {
                    k3 = z;
                    g_ws[j2] = wcur + h * (k1 - k2 + z);
                } else {
                    wcur += h * 0.125f * (k1 + 3.f * (k2 + k3) + z);
                    g_w[j2] = wcur;
                }
            }
        }
        if (stage != 4 * (T_STEPS - 1) - 1) {
            tgt += NB_ODE;
            gridsync(tgt);
        }
    }
}

// ---------------- xw: z[n] = dis[n] * (x_last[n] @ W_T), stored fp16 ----------------
// FFMA2 GEMM: x tile staged duplicated ((a,a) u64), weights as packed pairs
__global__ __launch_bounds__(256)
void xw_kernel(const float* __restrict__ xlast, int n) {
    __shared__ float Ws[64 * 64];
    __shared__ u64   xd[64 * 64];     // 32KB dup'd activations
    int n0 = blockIdx.x * 64;
    for (int i = threadIdx.x; i < 4096; i += 256) Ws[i] = g_w[i];
    for (int i = threadIdx.x; i < 4096; i += 256) {
        int r = i >> 6, c = i & 63, nn = n0 + r;
        xd[i] = dup2((nn < n) ? xlast[(size_t)nn * 64 + c] : 0.f);
    }
    __syncthreads();
    int tx = threadIdx.x & 15, ty = threadIdx.x >> 4;
    u64 accP[4][2];
#pragma unroll
    for (int i = 0; i < 4; ++i) { accP[i][0] = 0ull; accP[i][1] = 0ull; }
#pragma unroll 4
    for (int k = 0; k < 64; ++k) {
        ulonglong2 b = *(const ulonglong2*)&Ws[k * 64 + tx * 4];
#pragma unroll
        for (int i = 0; i < 4; ++i) {
            u64 a = xd[(ty * 4 + i) * 64 + k];
            FMA2(accP[i][0], a, b.x);
            FMA2(accP[i][1], a, b.y);
        }
    }
#pragma unroll
    for (int i = 0; i < 4; ++i) {
        int nn = n0 + ty * 4 + i;
        if (nn < n) {
            float dn = g_dis[nn];
            float2 p0 = unpack2(accP[i][0]);
            float2 p1 = unpack2(accP[i][1]);
            __half2 h0 = __floats2half2_rn(dn * p0.x, dn * p0.y);
            __half2 h1 = __floats2half2_rn(dn * p1.x, dn * p1.y);
            uint2 pk = make_uint2(*(unsigned*)&h0, *(unsigned*)&h1);
            *(uint2*)&g_zh[(size_t)nn * 32 + tx * 2] = pk;
        }
    }
}

// ---------------- fused gather + hA/hB (FFMA2 GEMM phase) ----------------
__global__ __launch_bounds__(256)
void gatherhab_kernel(const float* __restrict__ mw1, const float* __restrict__ mb1,
                      int n) {
    __shared__ float Ws[64 * 64];
    __shared__ u64   xd[64 * 64];     // 32KB dup'd relu'd rows
    const int tid  = threadIdx.x;
    const int lane = tid & 31;
    const int warp = tid >> 5;
    const int n0   = blockIdx.x * 64;

    // phase 1: each warp gathers 8 nodes; write dup'd relu'd values
#pragma unroll 1
    for (int i = 0; i < 8; ++i) {
        int local = warp * 8 + i;
        int nn = n0 + local;
        float2 s = make_float2(0.f, 0.f);
        float dc = 0.f;
        if (nn < n) {
            int k0 = g_base[nn], k1 = g_base[nn + 1];
            s = __half22float2(g_zh[(size_t)nn * 32 + lane]);   // self-loop term
            for (int kb = k0; kb < k1; kb += 32) {
                int m = k1 - kb; if (m > 32) m = 32;
                int rl = (lane < m) ? __ldg(&g_src[kb + lane]) : 0;
#pragma unroll 4
                for (int j = 0; j < m; ++j) {
                    int r = __shfl_sync(0xffffffffu, rl, j);
                    float2 v = __half22float2(g_zh[(size_t)r * 32 + lane]);
                    s.x += v.x; s.y += v.y;
                }
            }
            dc = g_dis[nn];
        }
        ulonglong2 wv;
        wv.x = dup2(fmaxf(dc * s.x, 0.f));
        wv.y = dup2(fmaxf(dc * s.y, 0.f));
        *(ulonglong2*)&xd[local * 64 + 2 * lane] = wv;
    }
    __syncthreads();

    // phase 2: hA = tile @ W[0:64] + b1 ; hB = tile @ W[64:128]  (FFMA2)
    int tx = tid & 15, ty = tid >> 4;
#pragma unroll
    for (int sel = 0; sel < 2; ++sel) {
        if (sel) __syncthreads();
        for (int i = tid; i < 4096; i += 256) Ws[i] = mw1[sel * 4096 + i];
        __syncthreads();
        u64 accP[4][2];
#pragma unroll
        for (int i = 0; i < 4; ++i) { accP[i][0] = 0ull; accP[i][1] = 0ull; }
#pragma unroll 4
        for (int k = 0; k < 64; ++k) {
            ulonglong2 b = *(const ulonglong2*)&Ws[k * 64 + tx * 4];
#pragma unroll
            for (int i = 0; i < 4; ++i) {
                u64 a = xd[(ty * 4 + i) * 64 + k];
                FMA2(accP[i][0], a, b.x);
                FMA2(accP[i][1], a, b.y);
            }
        }
        float4 bb = make_float4(0.f, 0.f, 0.f, 0.f);
        if (sel == 0) {
            bb.x = mb1[tx * 4 + 0]; bb.y = mb1[tx * 4 + 1];
            bb.z = mb1[tx * 4 + 2]; bb.w = mb1[tx * 4 + 3];
        }
        __half2* out = sel ? g_hBh : g_hAh;
#pragma unroll
        for (int i = 0; i < 4; ++i) {
            int nn = n0 + ty * 4 + i;
            if (nn < n) {
                float2 p0 = unpack2(accP[i][0]);
                float2 p1 = unpack2(accP[i][1]);
                __half2 h0 = __floats2half2_rn(p0.x + bb.x, p0.y + bb.y);
                __half2 h1 = __floats2half2_rn(p1.x + bb.z, p1.y + bb.w);
                uint2 pk = make_uint2(*(unsigned*)&h0, *(unsigned*)&h1);
                *(uint2*)&out[(size_t)nn * 32 + tx * 2] = pk;
            }
        }
    }
}

// ---------------- edge MLP: out[e] = relu(hA[r]+hB[c]+ea@C) . w2 + b2 ----------------
// block = 256 threads / 64 edges; FFMA2 with dup'd ea staged in smem
__global__ __launch_bounds__(256)
void edge_kernel(const float* __restrict__ ea, const int* __restrict__ ei,
                 const float* __restrict__ mw1, const float* __restrict__ w2,
                 const float* __restrict__ b2, float* __restrict__ out, int e) {
    __shared__ __align__(16) u64 sdup[EPB * 16];   // 8KB (a,a) pairs
    __shared__ int   sr[EPB], sc[EPB];
    __shared__ float sout[EPB];
    const int tid  = threadIdx.x;
    const int lane = tid & 31;
    const int warp = tid >> 5;
    const int e0   = blockIdx.x * EPB;
    const int valid = (e - e0 < EPB) ? (e - e0) : EPB;

    // edge-invariant C columns packed (c0[f], c1[f]) per lane
    u64 cp[16];
#pragma unroll
    for (int f = 0; f < 16; ++f)
        cp[f] = *(const u64*)&mw1[(128 + f) * 64 + 2 * lane];
    const float2 w2p = *(const float2*)&w2[2 * lane];
    const float  bb  = __ldg(&b2[0]);

    // stage dup'd ea + indices
    for (int i = tid; i < valid * 16; i += 256)
        sdup[i] = dup2(__ldg(&ea[(size_t)e0 * 16 + i]));
    if (tid < valid)                sr[tid]       = __ldg(&ei[e0 + tid]);
    else if (tid >= EPB && tid < EPB + valid) sc[tid - EPB] = __ldg(&ei[e + e0 + (tid - EPB)]);
    __syncthreads();

    if (valid == EPB) {
#pragma unroll 1
        for (int it = 0; it < 8; it += 2) {
            int le0 = warp * 8 + it, le1 = le0 + 1;
            int r0 = sr[le0], cc0 = sc[le0];
            int r1 = sr[le1], cc1 = sc[le1];
            float2 fa0 = __half22float2(g_hAh[(size_t)r0 * 32 + lane]);
            float2 fb0 = __half22float2(g_hBh[(size_t)cc0 * 32 + lane]);
            float2 fa1 = __half22float2(g_hAh[(size_t)r1 * 32 + lane]);
            float2 fb1 = __half22float2(g_hBh[(size_t)cc1 * 32 + lane]);
            u64 sP0 = pack2(fa0.x + fb0.x, fa0.y + fb0.y);
            u64 sP1 = pack2(fa1.x + fb1.x, fa1.y + fb1.y);
            const ulonglong2* ap0 = (const ulonglong2*)&sdup[le0 * 16];
            const ulonglong2* ap1 = (const ulonglong2*)&sdup[le1 * 16];
#pragma unroll
            for (int q = 0; q < 8; ++q) {
                ulonglong2 a0 = ap0[q];
                ulonglong2 a1 = ap1[q];
                FMA2(sP0, a0.x, cp[2 * q]);
                FMA2(sP1, a1.x, cp[2 * q]);
                FMA2(sP0, a0.y, cp[2 * q + 1]);
                FMA2(sP1, a1.y, cp[2 * q + 1]);
            }
            float2 s0 = unpack2(sP0);
            float2 s1 = unpack2(sP1);
            float p0 = fmaxf(s0.x, 0.f) * w2p.x + fmaxf(s0.y, 0.f) * w2p.y;
            float p1 = fmaxf(s1.x, 0.f) * w2p.x + fmaxf(s1.y, 0.f) * w2p.y;
#pragma unroll
            for (int o = 16; o; o >>= 1) {
                p0 += __shfl_xor_sync(0xffffffffu, p0, o);
                p1 += __shfl_xor_sync(0xffffffffu, p1, o);
            }
            if (lane == 0) { sout[le0] = p0 + bb; sout[le1] = p1 + bb; }
        }
    } else {
        for (int it = 0; it < 8; ++it) {
            int le = warp * 8 + it;
            if (le < valid) {
                int r = sr[le], c = sc[le];
                float2 fa = __half22float2(g_hAh[(size_t)r * 32 + lane]);
                float2 fb = __half22float2(g_hBh[(size_t)c * 32 + lane]);
                u64 sP = pack2(fa.x + fb.x, fa.y + fb.y);
                const ulonglong2* ap = (const ulonglong2*)&sdup[le * 16];
#pragma unroll
                for (int q = 0; q < 8; ++q) {
                    ulonglong2 a = ap[q];
                    FMA2(sP, a.x, cp[2 * q]);
                    FMA2(sP, a.y, cp[2 * q + 1]);
                }
                float2 s = unpack2(sP);
                float p = fmaxf(s.x, 0.f) * w2p.x + fmaxf(s.y, 0.f) * w2p.y;
#pragma unroll
                for (int o = 16; o; o >>= 1) p += __shfl_xor_sync(0xffffffffu, p, o);
                if (lane == 0) sout[le] = p + bb;
            }
        }
    }
    __syncthreads();
    if (tid < valid) out[e0 + tid] = sout[tid];
}

// ---------------- launcher ----------------
extern "C" void kernel_launch(void* const* d_in, const int* in_sizes, int n_in,
                              void* d_out, int out_size) {
    const float* x_seq = (const float*)d_in[0];
    const float* ea    = (const float*)d_in[1];
    const float* iw    = (const float*)d_in[2];
    const float* W1    = (const float*)d_in[3];
    const float* b1o   = (const float*)d_in[4];
    const float* W2    = (const float*)d_in[5];
    const float* b2o   = (const float*)d_in[6];
    const float* mw1   = (const float*)d_in[7];
    const float* mb1   = (const float*)d_in[8];
    const float* mw2   = (const float*)d_in[9];
    const float* mb2   = (const float*)d_in[10];
    const int*   ei    = (const int*)d_in[11];
    float* out = (float*)d_out;

    const int n = NN;
    const int e = EE;
    const float* xlast = x_seq + (size_t)(T_STEPS - 1) * n * 64;
    const float h = 1.0f / (float)(T_STEPS - 1);

    cudaFuncSetAttribute(ode_persist, cudaFuncAttributeMaxDynamicSharedMemorySize,
                         ODE_SMEM_FLOATS * 4);

    cudaStream_t sB;
    cudaStreamCreateWithFlags(&sB, cudaStreamNonBlocking);
    cudaEvent_t evFork, evInit, evJoin;
    cudaEventCreateWithFlags(&evFork, cudaEventDisableTiming);
    cudaEventCreateWithFlags(&evInit, cudaEventDisableTiming);
    cudaEventCreateWithFlags(&evJoin, cudaEventDisableTiming);

    // main: weight transposes (dependency-free) start immediately
    {
        float* w1t; cudaGetSymbolAddress((void**)&w1t, g_W1t);
        float* w2t; cudaGetSymbolAddress((void**)&w2t, g_W2t);
        dim3 t1g(BN / 32, FLAT / 32);
        transpose_kernel<<<t1g, dim3(32, 8)>>>(W1, w1t, FLAT, BN);
        dim3 t2g(FLAT / 32, BN / 32);
        transpose_kernel<<<t2g, dim3(32, 8)>>>(W2, w2t, BN, FLAT);
    }
    // FORK: sB joins the capture graph by waiting on an event recorded in
    // the capturing (default) stream — required for stream-capture legality.
    cudaEventRecord(evFork, 0);
    cudaStreamWaitEvent(sB, evFork, 0);

    // stream B: init + whole CSR/normalization chain
    init_kernel<<<(n + 255) / 256, 256, 0, sB>>>(iw, n);
    cudaEventRecord(evInit, sB);
    count_kernel<<<(e + 255) / 256, 256, 0, sB>>>(ei, e);
    dis_kernel<<<(n + 255) / 256, 256, 0, sB>>>(n);
    scan1_kernel<<<NB_SCAN, 1024, 0, sB>>>(n);
    scan2_kernel<<<1, 128, 0, sB>>>(NB_SCAN);
    scan3_kernel<<<NB_SCAN, 1024, 0, sB>>>(n);
    place_kernel<<<(e + 255) / 256, 256, 0, sB>>>(ei, e);
    cudaEventRecord(evJoin, sB);

    // main: ODE starts as soon as init (g_w/g_barcnt) is done; CSR chain
    // continues concurrently on sB under the ODE.
    cudaStreamWaitEvent(0, evInit, 0);
    ode_persist<<<NB_ODE, 1024, ODE_SMEM_FLOATS * 4>>>(b1o, b2o, h);

    // JOIN: GCN needs g_dis + CSR from sB
    cudaStreamWaitEvent(0, evJoin, 0);
    xw_kernel<<<(n + 63) / 64, 256>>>(xlast, n);
    gatherhab_kernel<<<(n + 63) / 64, 256>>>(mw1, mb1, n);
    edge_kernel<<<(e + EPB - 1) / EPB, 256>>>(ea, ei, mw1, mw2, mb2, out, e);

    cudaEventDestroy(evFork);
    cudaEventDestroy(evInit);
    cudaEventDestroy(evJoin);
    cudaStreamDestroy(sB);
}